// round 8
// baseline (speedup 1.0000x reference)
#include <cuda_runtime.h>
#include <cstdint>
#include <math.h>

#define NB 16384
#define NLOC 12
#define NF 512
#define NH 256
#define SCALE 0.0625f

// Scratch (device globals: allocation-free rule)
__device__ float g_T[(size_t)NB * NF];       // 32 MB
__device__ float g_pooled[(size_t)NB * NF];  // 32 MB (tf32-pre-rounded)
__device__ float g_lfG[(size_t)NB * NF];     // 32 MB
__device__ float g_Gt[(size_t)NB * NF];      // 32 MB: f2tf(G)
__device__ float g_M3[NF * NF];              // tf32-rounded Wq @ Wk^T
__device__ float g_Mcat[2 * NF * NF];        // tf32-rounded [Wv@Wf_top ; S*Wv@Wf_bot]
__device__ float g_c[NF];

__device__ __forceinline__ uint32_t f2tf(float x) {
    uint32_t y;
    asm("cvt.rna.tf32.f32 %0, %1;" : "=r"(y) : "f"(x));
    return y;
}

__device__ __forceinline__ void cpa16(void* dst_smem, const void* src) {
    uint32_t d = (uint32_t)__cvta_generic_to_shared(dst_smem);
    asm volatile("cp.async.cg.shared.global [%0], [%1], 16;" :: "r"(d), "l"(src));
}
__device__ __forceinline__ void cpa_commit() {
    asm volatile("cp.async.commit_group;");
}
template <int N>
__device__ __forceinline__ void cpa_wait() {
    asm volatile("cp.async.wait_group %0;" :: "n"(N));
}

__device__ __forceinline__ void mma8(float* c, const uint32_t* a, const uint32_t* b) {
    asm volatile(
        "mma.sync.aligned.m16n8k8.row.col.f32.tf32.tf32.f32 "
        "{%0,%1,%2,%3}, {%4,%5,%6,%7}, {%8,%9}, {%0,%1,%2,%3};"
        : "+f"(c[0]), "+f"(c[1]), "+f"(c[2]), "+f"(c[3])
        : "r"(a[0]), "r"(a[1]), "r"(a[2]), "r"(a[3]), "r"(b[0]), "r"(b[1]));
}

constexpr int BM = 128, BN = 64, BK = 16;
constexpr int ASTR = 20;  // floats per A smem row (bank-conflict-free frag loads)
constexpr int BSTR = 72;  // floats per B smem row (72 mod 32 == 8 -> conflict-free)
constexpr int STG = 3;    // 3-stage cp.async pipeline

// GEMM tile body: C[BMxBN at (by,bx)] = alpha * A[M,K] @ B[K,N]
// BT: B source is [N,K] (transposed), loaded via LDG+STS.
// CONCAT: A rows are [A | A2] along K (split at NF).
// FUSE: C = relu(acc + cvec[n]) + lfG[m,n].
// CCVT: apply tf32 rounding on consume (inputs are raw fp32).
//       If false, inputs MUST already be tf32-pre-rounded (bit pass-through).
// SCVT: tf32-round outputs on store (for matrices feeding later CCVT=false GEMMs).
template <bool BT, bool CONCAT, bool FUSE, bool CCVT, bool SCVT>
__device__ __forceinline__ void gemm_body(
    const float* __restrict__ A, int lda,
    const float* __restrict__ A2,
    const float* __restrict__ B, int ldb,
    float* __restrict__ C, int ldc,
    int K, float alpha,
    const float* __restrict__ cvec,
    const float* __restrict__ lfG,
    int bx, int by, float* sA, float* sB)
{
    const int tid = threadIdx.x;
    const int m0 = by * BM;
    const int n0 = bx * BN;
    const int warp = tid >> 5, lane = tid & 31;
    const int wm = warp & 3, wn = warp >> 2;   // 4 x 2 warp grid, 32x32 warp tile
    const int grp = lane >> 2, qid = lane & 3;

    const int ar0 = tid >> 2, ac0 = (tid & 3) * 4;
    const int ar1 = (tid + 256) >> 2;
    const int bk0 = tid >> 4, bn0 = (tid & 15) * 4;
    const int tn = tid >> 2, tk = (tid & 3) * 4;

    float acc[2][4][4];
#pragma unroll
    for (int i = 0; i < 2; i++)
#pragma unroll
        for (int j = 0; j < 4; j++)
#pragma unroll
            for (int l = 0; l < 4; l++) acc[i][j][l] = 0.f;

    const int niter = K / BK;

    auto issue = [&](int s, int k0) {
        const float* Ap = A;
        int kA = k0;
        if (CONCAT && k0 >= NF) { Ap = A2; kA = k0 - NF; }
        cpa16(&sA[((size_t)s * BM + ar0) * ASTR + ac0],
              Ap + (size_t)(m0 + ar0) * lda + kA + ac0);
        cpa16(&sA[((size_t)s * BM + ar1) * ASTR + ac0],
              Ap + (size_t)(m0 + ar1) * lda + kA + ac0);
        if (!BT) {
            cpa16(&sB[((size_t)s * BK + bk0) * BSTR + bn0],
                  B + (size_t)(k0 + bk0) * ldb + n0 + bn0);
        } else {
            float4 v = *(const float4*)(B + (size_t)(n0 + tn) * ldb + k0 + tk);
            sB[((size_t)s * BK + tk + 0) * BSTR + tn] = v.x;
            sB[((size_t)s * BK + tk + 1) * BSTR + tn] = v.y;
            sB[((size_t)s * BK + tk + 2) * BSTR + tn] = v.z;
            sB[((size_t)s * BK + tk + 3) * BSTR + tn] = v.w;
        }
        cpa_commit();
    };

    // consume: cvt only if CCVT, else raw bit pass-through
    auto ld = [&](const float* p) -> uint32_t {
        float v = *p;
        return CCVT ? f2tf(v) : __float_as_uint(v);
    };

    issue(0, 0);
    issue(1, BK);

    for (int it = 0; it < niter; it++) {
        const int cur = it % STG;
        if (it + 2 < niter) {
            issue((it + 2) % STG, (it + 2) * BK);
            cpa_wait<2>();
        } else if (it + 1 < niter) {
            cpa_wait<1>();
        } else {
            cpa_wait<0>();
        }
        __syncthreads();

        const float* As = &sA[(size_t)cur * BM * ASTR];
        const float* Bs = &sB[(size_t)cur * BK * BSTR];
#pragma unroll
        for (int kk = 0; kk < BK; kk += 8) {
            uint32_t a[2][4], b[4][2];
#pragma unroll
            for (int mi = 0; mi < 2; mi++) {
                int m = wm * 32 + mi * 16;
                a[mi][0] = ld(&As[(m + grp) * ASTR + kk + qid]);
                a[mi][1] = ld(&As[(m + grp + 8) * ASTR + kk + qid]);
                a[mi][2] = ld(&As[(m + grp) * ASTR + kk + qid + 4]);
                a[mi][3] = ld(&As[(m + grp + 8) * ASTR + kk + qid + 4]);
            }
#pragma unroll
            for (int ni = 0; ni < 4; ni++) {
                int n = wn * 32 + ni * 8;
                b[ni][0] = ld(&Bs[(kk + qid) * BSTR + n + grp]);
                b[ni][1] = ld(&Bs[(kk + qid + 4) * BSTR + n + grp]);
            }
#pragma unroll
            for (int mi = 0; mi < 2; mi++)
#pragma unroll
                for (int ni = 0; ni < 4; ni++) mma8(acc[mi][ni], a[mi], b[ni]);
        }
        __syncthreads();
    }

#pragma unroll
    for (int mi = 0; mi < 2; mi++) {
#pragma unroll
        for (int ni = 0; ni < 4; ni++) {
            int r = m0 + wm * 32 + mi * 16 + grp;
            int cn = n0 + wn * 32 + ni * 8 + qid * 2;
            size_t o0 = (size_t)r * ldc + cn;
            size_t o1 = (size_t)(r + 8) * ldc + cn;
            if (!FUSE) {
                float s0 = alpha * acc[mi][ni][0], s1 = alpha * acc[mi][ni][1];
                float s2 = alpha * acc[mi][ni][2], s3 = alpha * acc[mi][ni][3];
                if (SCVT) {
                    s0 = __uint_as_float(f2tf(s0));
                    s1 = __uint_as_float(f2tf(s1));
                    s2 = __uint_as_float(f2tf(s2));
                    s3 = __uint_as_float(f2tf(s3));
                }
                *(float2*)(C + o0) = make_float2(s0, s1);
                *(float2*)(C + o1) = make_float2(s2, s3);
            } else {
                float c0 = cvec[cn], c1 = cvec[cn + 1];
                float2 v0, v1;
                v0.x = fmaxf(acc[mi][ni][0] + c0, 0.f) + lfG[o0];
                v0.y = fmaxf(acc[mi][ni][1] + c1, 0.f) + lfG[o0 + 1];
                v1.x = fmaxf(acc[mi][ni][2] + c0, 0.f) + lfG[o1];
                v1.y = fmaxf(acc[mi][ni][3] + c1, 0.f) + lfG[o1 + 1];
                *(float2*)(C + o0) = v0;
                *(float2*)(C + o1) = v1;
            }
        }
    }
}

// Big GEMM wrapper: operands pre-rounded to tf32 -> no consume cvt.
// Grid: x = N-tile (fast -> L2 A reuse), y = M-tile.
template <bool CONCAT, bool FUSE>
__global__ __launch_bounds__(256, 2) void gemm_big(
    const float* __restrict__ A, int lda,
    const float* __restrict__ A2,
    const float* __restrict__ B, int ldb,
    float* __restrict__ C, int ldc, int K,
    const float* __restrict__ cvec,
    const float* __restrict__ lfG)
{
    __shared__ float sA[STG * BM * ASTR];
    __shared__ float sB[STG * BK * BSTR];
    gemm_body<false, CONCAT, FUSE, false, false>(
        A, lda, A2, B, ldb, C, ldc, K, 1.f,
        cvec, lfG, blockIdx.x, blockIdx.y, sA, sB);
}

// Fused precompute (2152 blocks):
//   0-31    M3 = Wq@Wk^T          (tf32-rounded store)
//   32-63   Mcat_top = Wv@Wf_top  (tf32-rounded store)
//   64-95   Mcat_bot = S*Wv@Wf_b  (tf32-rounded store)
//   96-103  cvec reduction
//   104+    g_Gt = f2tf(G)        (runs on SMs idle during the small GEMMs)
__global__ __launch_bounds__(256, 2) void k_pre(
    const float* __restrict__ Wq, const float* __restrict__ Wk,
    const float* __restrict__ Wv, const float* __restrict__ bv,
    const float* __restrict__ Wf, const float* __restrict__ bf,
    const float* __restrict__ wdr, const float* __restrict__ bdr,
    const float* __restrict__ G)
{
    __shared__ float sA[STG * BM * ASTR];
    __shared__ float sB[STG * BK * BSTR];
    const int b = blockIdx.x;
    if (b < 96) {
        const int g = b & 31;
        const int bx = g & 7, by = g >> 3;   // 8 N-tiles x 4 M-tiles
        if (b < 32) {
            gemm_body<true, false, false, true, true>(
                Wq, NH, nullptr, Wk, NH, g_M3, NF, NH,
                1.f, nullptr, nullptr, bx, by, sA, sB);
        } else if (b < 64) {
            gemm_body<false, false, false, true, true>(
                Wv, NH, nullptr, Wf, NF, g_Mcat, NF, NH,
                1.f, nullptr, nullptr, bx, by, sA, sB);
        } else {
            float S = 0.f;
#pragma unroll
            for (int k = 0; k < NLOC; k++) S += wdr[k];
            gemm_body<false, false, false, true, true>(
                Wv, NH, nullptr, Wf + (size_t)NH * NF, NF,
                g_Mcat + (size_t)NF * NF, NF, NH,
                S, nullptr, nullptr, bx, by, sA, sB);
        }
    } else if (b < 104) {
        // cvec: c[f] = bf + bv@Wf_top + S*bv@Wf_bot + b_dr*colsum(Wf_bot)
        __shared__ float red[3][4][64];
        const int t = threadIdx.x;
        const int fl = t & 63;
        const int f = (b - 96) * 64 + fl;
        const int hc = t >> 6;
        float a1 = 0.f, a2 = 0.f, a3 = 0.f;
        for (int h = hc * 64; h < hc * 64 + 64; h++) {
            float w1 = Wf[(size_t)h * NF + f];
            float w2 = Wf[(size_t)(NH + h) * NF + f];
            float bvh = bv[h];
            a1 += bvh * w1;
            a2 += bvh * w2;
            a3 += w2;
        }
        red[0][hc][fl] = a1;
        red[1][hc][fl] = a2;
        red[2][hc][fl] = a3;
        __syncthreads();
        if (hc == 0) {
            float s1 = red[0][0][fl] + red[0][1][fl] + red[0][2][fl] + red[0][3][fl];
            float s2 = red[1][0][fl] + red[1][1][fl] + red[1][2][fl] + red[1][3][fl];
            float s3 = red[2][0][fl] + red[2][1][fl] + red[2][2][fl] + red[2][3][fl];
            float S = 0.f;
#pragma unroll
            for (int k = 0; k < NLOC; k++) S += wdr[k];
            g_c[f] = bf[f] + s1 + S * s2 + (*bdr) * s3;
        }
    } else {
        // g_Gt = f2tf(G): 2048 blocks x 256 threads x 4 strided float4 = 8M floats
        const float4* src = (const float4*)G;
        float4* dst = (float4*)g_Gt;
#pragma unroll
        for (int i = 0; i < 4; i++) {
            size_t idx = (size_t)(b - 104) * 256 + threadIdx.x + (size_t)i * 2048 * 256;
            float4 v = src[idx];
            float4 o;
            o.x = __uint_as_float(f2tf(v.x));
            o.y = __uint_as_float(f2tf(v.y));
            o.z = __uint_as_float(f2tf(v.z));
            o.w = __uint_as_float(f2tf(v.w));
            dst[idx] = o;
        }
    }
}

// Per-row: scores vs T, softmax over 12, pooled = sum a_k * local_k (tf32-rounded),
// lfG = sum w_dr_k * local_k + b_dr + G   (local read exactly once via smem)
__global__ __launch_bounds__(128) void k_attn(
    const float* __restrict__ G, const float* __restrict__ L,
    const float* __restrict__ wdr, const float* __restrict__ bdr)
{
    __shared__ float4 sL[NLOC * 128];
    __shared__ float4 sT[128];
    __shared__ float sd[NLOC];
    const int b = blockIdx.x, tid = threadIdx.x;
    const float4* Lr = (const float4*)(L + (size_t)b * NLOC * NF);
    sT[tid] = ((const float4*)(g_T + (size_t)b * NF))[tid];
#pragma unroll
    for (int k = 0; k < NLOC; k++) sL[k * 128 + tid] = Lr[k * 128 + tid];
    __syncthreads();

    const int warp = tid >> 5, lane = tid & 31;
#pragma unroll
    for (int kk = 0; kk < 3; kk++) {
        int k = warp * 3 + kk;
        float s = 0.f;
#pragma unroll
        for (int j = 0; j < 4; j++) {
            float4 x = sL[k * 128 + lane + j * 32];
            float4 t = sT[lane + j * 32];
            s += x.x * t.x + x.y * t.y + x.z * t.z + x.w * t.w;
        }
#pragma unroll
        for (int o = 16; o; o >>= 1) s += __shfl_xor_sync(0xffffffffu, s, o);
        if (lane == 0) sd[k] = s;
    }
    __syncthreads();

    float a[NLOC], mx = -1e30f;
#pragma unroll
    for (int k = 0; k < NLOC; k++) mx = fmaxf(mx, sd[k]);
    float sum = 0.f;
#pragma unroll
    for (int k = 0; k < NLOC; k++) { a[k] = __expf((sd[k] - mx) * SCALE); sum += a[k]; }
    float inv = 1.f / sum;

    float4 p = make_float4(0, 0, 0, 0), q = make_float4(0, 0, 0, 0);
#pragma unroll
    for (int k = 0; k < NLOC; k++) {
        float ak = a[k] * inv, wk = wdr[k];
        float4 x = sL[k * 128 + tid];
        p.x += ak * x.x; p.y += ak * x.y; p.z += ak * x.z; p.w += ak * x.w;
        q.x += wk * x.x; q.y += wk * x.y; q.z += wk * x.z; q.w += wk * x.w;
    }
    float bd = *bdr;
    float4 g = ((const float4*)(G + (size_t)b * NF))[tid];
    float4 pt;
    pt.x = __uint_as_float(f2tf(p.x));
    pt.y = __uint_as_float(f2tf(p.y));
    pt.z = __uint_as_float(f2tf(p.z));
    pt.w = __uint_as_float(f2tf(p.w));
    ((float4*)(g_pooled + (size_t)b * NF))[tid] = pt;
    float4 o;
    o.x = q.x + bd + g.x; o.y = q.y + bd + g.y;
    o.z = q.z + bd + g.z; o.w = q.w + bd + g.w;
    ((float4*)(g_lfG + (size_t)b * NF))[tid] = o;
}

extern "C" void kernel_launch(void* const* d_in, const int* in_sizes, int n_in,
                              void* d_out, int out_size)
{
    const float* G   = (const float*)d_in[0];
    const float* L   = (const float*)d_in[1];
    const float* Wq  = (const float*)d_in[2];
    // d_in[3] = bq (unused: drops out of softmax)
    const float* Wk  = (const float*)d_in[4];
    // d_in[5] = bk (unused: k-independent score shift cancels in softmax)
    const float* Wv  = (const float*)d_in[6];
    const float* bv  = (const float*)d_in[7];
    const float* wdr = (const float*)d_in[8];
    const float* bdr = (const float*)d_in[9];
    const float* Wf  = (const float*)d_in[10];
    const float* bf  = (const float*)d_in[11];
    float* out = (float*)d_out;

    float *T, *P, *LF, *Gt, *M3, *Mcat, *cvec;
    cudaGetSymbolAddress((void**)&T, g_T);
    cudaGetSymbolAddress((void**)&P, g_pooled);
    cudaGetSymbolAddress((void**)&LF, g_lfG);
    cudaGetSymbolAddress((void**)&Gt, g_Gt);
    cudaGetSymbolAddress((void**)&M3, g_M3);
    cudaGetSymbolAddress((void**)&Mcat, g_Mcat);
    cudaGetSymbolAddress((void**)&cvec, g_c);

    dim3 blk(256);
    dim3 gbig(NF / 64, NB / 128);   // x = N-tiles (8), y = M-tiles (128)

    // 1) fused precompute: M3, Mcat, cvec, and g_Gt = f2tf(G)  [one launch]
    k_pre<<<104 + 2048, blk>>>(Wq, Wk, Wv, bv, Wf, bf, wdr, bdr, G);

    // 2) T = Gt @ M3   [16384,512] x [512,512]   (pre-rounded operands)
    gemm_big<false, false><<<gbig, blk>>>(
        Gt, NF, nullptr, M3, NF, T, NF, NF, nullptr, nullptr);

    // 3) per-row softmax / pooling (reads local_features once)
    k_attn<<<NB, 128>>>(G, L, wdr, bdr);

    // 4) OUT = relu([pooled | Gt] @ Mcat + c) + lfG   [16384,1024] x [1024,512]
    gemm_big<true, true><<<gbig, blk>>>(
        P, NF, Gt, Mcat, NF, out, NF, 2 * NF, cvec, LF);
}

// round 13
// speedup vs baseline: 1.0976x; 1.0976x over previous
#include <cuda_runtime.h>
#include <cstdint>
#include <math.h>

#define NB 16384
#define NLOC 12
#define NF 512
#define NH 256
#define SCALE 0.0625f

// Scratch (device globals: allocation-free rule)
__device__ float g_T[(size_t)NB * NF];       // 32 MB
__device__ float g_pooled[(size_t)NB * NF];  // 32 MB (tf32-pre-rounded)
__device__ float g_lfG[(size_t)NB * NF];     // 32 MB
__device__ float g_Gt[(size_t)NB * NF];      // 32 MB: f2tf(G)
__device__ float g_M3[NF * NF];              // tf32-rounded Wq @ Wk^T
__device__ float g_Mcat[2 * NF * NF];        // tf32-rounded [Wv@Wf_top ; S*Wv@Wf_bot]
__device__ float g_c[NF];

__device__ __forceinline__ uint32_t f2tf(float x) {
    uint32_t y;
    asm("cvt.rna.tf32.f32 %0, %1;" : "=r"(y) : "f"(x));
    return y;
}

__device__ __forceinline__ void cpa16(void* dst_smem, const void* src) {
    uint32_t d = (uint32_t)__cvta_generic_to_shared(dst_smem);
    asm volatile("cp.async.cg.shared.global [%0], [%1], 16;" :: "r"(d), "l"(src));
}
__device__ __forceinline__ void cpa_commit() {
    asm volatile("cp.async.commit_group;");
}
template <int N>
__device__ __forceinline__ void cpa_wait() {
    asm volatile("cp.async.wait_group %0;" :: "n"(N));
}

__device__ __forceinline__ void mma8(float* c, const uint32_t* a, const uint32_t* b) {
    asm volatile(
        "mma.sync.aligned.m16n8k8.row.col.f32.tf32.tf32.f32 "
        "{%0,%1,%2,%3}, {%4,%5,%6,%7}, {%8,%9}, {%0,%1,%2,%3};"
        : "+f"(c[0]), "+f"(c[1]), "+f"(c[2]), "+f"(c[3])
        : "r"(a[0]), "r"(a[1]), "r"(a[2]), "r"(a[3]), "r"(b[0]), "r"(b[1]));
}

constexpr int BM = 128, BN = 128, BK = 16;
constexpr int ASTR = 20;   // floats per A smem row (conflict-free frag loads)
constexpr int BSTR = 136;  // floats per B smem row (136 mod 32 == 8 -> conflict-free)
constexpr int STG = 3;     // 3-stage cp.async pipeline
constexpr int SMEM_FLOATS_A = STG * BM * ASTR;           // 7680
constexpr int SMEM_FLOATS_B = STG * BK * BSTR;           // 6528
constexpr int SMEM_BYTES = (SMEM_FLOATS_A + SMEM_FLOATS_B) * 4;  // 56832 (> 48KB -> dynamic)

// GEMM tile body: C[BMxBN at (by,bx)] = alpha * A[M,K] @ B[K,N]
// Warp layout: 8 warps as 2(M) x 4(N); 64x32 per warp (16 MMAs / kk-step).
// BT: B source is [N,K] (transposed), loaded via LDG+STS.
// CONCAT: A rows are [A | A2] along K (split at NF).
// FUSE: C = relu(acc + cvec[n]) + lfG[m,n].
// CCVT: tf32-round on consume (raw fp32 inputs); else bit pass-through.
// SCVT: tf32-round outputs on store.
template <bool BT, bool CONCAT, bool FUSE, bool CCVT, bool SCVT>
__device__ __forceinline__ void gemm_body(
    const float* __restrict__ A, int lda,
    const float* __restrict__ A2,
    const float* __restrict__ B, int ldb,
    float* __restrict__ C, int ldc,
    int K, float alpha,
    const float* __restrict__ cvec,
    const float* __restrict__ lfG,
    int bx, int by, float* sA, float* sB)
{
    const int tid = threadIdx.x;
    const int m0 = by * BM;
    const int n0 = bx * BN;
    const int warp = tid >> 5, lane = tid & 31;
    const int wm = warp >> 2, wn = warp & 3;   // 2 x 4 warp grid, 64x32 warp tile
    const int grp = lane >> 2, qid = lane & 3;

    // A: 128x16 tile = 512 float4, 2/thread
    const int ar0 = tid >> 2, ac0 = (tid & 3) * 4;
    const int ar1 = (tid + 256) >> 2;
    // B (!BT): 16x128 tile = 512 float4, 2/thread
    const int bk0 = tid >> 5, bn0 = (tid & 31) * 4;
    const int bk1 = (tid + 256) >> 5;
    // B (BT): 128 rows x 16 cols = 512 float4, 2/thread
    const int tn0 = tid >> 2, tk0 = (tid & 3) * 4;
    const int tn1 = (tid + 256) >> 2;

    float acc[4][4][4];
#pragma unroll
    for (int i = 0; i < 4; i++)
#pragma unroll
        for (int j = 0; j < 4; j++)
#pragma unroll
            for (int l = 0; l < 4; l++) acc[i][j][l] = 0.f;

    const int niter = K / BK;

    auto issue = [&](int s, int k0) {
        const float* Ap = A;
        int kA = k0;
        if (CONCAT && k0 >= NF) { Ap = A2; kA = k0 - NF; }
        cpa16(&sA[((size_t)s * BM + ar0) * ASTR + ac0],
              Ap + (size_t)(m0 + ar0) * lda + kA + ac0);
        cpa16(&sA[((size_t)s * BM + ar1) * ASTR + ac0],
              Ap + (size_t)(m0 + ar1) * lda + kA + ac0);
        if (!BT) {
            cpa16(&sB[((size_t)s * BK + bk0) * BSTR + bn0],
                  B + (size_t)(k0 + bk0) * ldb + n0 + bn0);
            cpa16(&sB[((size_t)s * BK + bk1) * BSTR + bn0],
                  B + (size_t)(k0 + bk1) * ldb + n0 + bn0);
        } else {
#pragma unroll
            for (int h = 0; h < 2; h++) {
                int tn = h ? tn1 : tn0;
                float4 v = *(const float4*)(B + (size_t)(n0 + tn) * ldb + k0 + tk0);
                sB[((size_t)s * BK + tk0 + 0) * BSTR + tn] = v.x;
                sB[((size_t)s * BK + tk0 + 1) * BSTR + tn] = v.y;
                sB[((size_t)s * BK + tk0 + 2) * BSTR + tn] = v.z;
                sB[((size_t)s * BK + tk0 + 3) * BSTR + tn] = v.w;
            }
        }
        cpa_commit();
    };

    auto ld = [&](const float* p) -> uint32_t {
        float v = *p;
        return CCVT ? f2tf(v) : __float_as_uint(v);
    };

    issue(0, 0);
    issue(1, BK);

    for (int it = 0; it < niter; it++) {
        const int cur = it % STG;
        if (it + 2 < niter) {
            issue((it + 2) % STG, (it + 2) * BK);
            cpa_wait<2>();
        } else if (it + 1 < niter) {
            cpa_wait<1>();
        } else {
            cpa_wait<0>();
        }
        __syncthreads();

        const float* As = &sA[(size_t)cur * BM * ASTR];
        const float* Bs = &sB[(size_t)cur * BK * BSTR];
#pragma unroll
        for (int kk = 0; kk < BK; kk += 8) {
            uint32_t a[4][4], b[4][2];
#pragma unroll
            for (int mi = 0; mi < 4; mi++) {
                int m = wm * 64 + mi * 16;
                a[mi][0] = ld(&As[(m + grp) * ASTR + kk + qid]);
                a[mi][1] = ld(&As[(m + grp + 8) * ASTR + kk + qid]);
                a[mi][2] = ld(&As[(m + grp) * ASTR + kk + qid + 4]);
                a[mi][3] = ld(&As[(m + grp + 8) * ASTR + kk + qid + 4]);
            }
#pragma unroll
            for (int ni = 0; ni < 4; ni++) {
                int n = wn * 32 + ni * 8;
                b[ni][0] = ld(&Bs[(kk + qid) * BSTR + n + grp]);
                b[ni][1] = ld(&Bs[(kk + qid + 4) * BSTR + n + grp]);
            }
#pragma unroll
            for (int mi = 0; mi < 4; mi++)
#pragma unroll
                for (int ni = 0; ni < 4; ni++) mma8(acc[mi][ni], a[mi], b[ni]);
        }
        __syncthreads();
    }

#pragma unroll
    for (int mi = 0; mi < 4; mi++) {
#pragma unroll
        for (int ni = 0; ni < 4; ni++) {
            int r = m0 + wm * 64 + mi * 16 + grp;
            int cn = n0 + wn * 32 + ni * 8 + qid * 2;
            size_t o0 = (size_t)r * ldc + cn;
            size_t o1 = (size_t)(r + 8) * ldc + cn;
            if (!FUSE) {
                float s0 = alpha * acc[mi][ni][0], s1 = alpha * acc[mi][ni][1];
                float s2 = alpha * acc[mi][ni][2], s3 = alpha * acc[mi][ni][3];
                if (SCVT) {
                    s0 = __uint_as_float(f2tf(s0));
                    s1 = __uint_as_float(f2tf(s1));
                    s2 = __uint_as_float(f2tf(s2));
                    s3 = __uint_as_float(f2tf(s3));
                }
                *(float2*)(C + o0) = make_float2(s0, s1);
                *(float2*)(C + o1) = make_float2(s2, s3);
            } else {
                float c0 = cvec[cn], c1 = cvec[cn + 1];
                float2 v0, v1;
                v0.x = fmaxf(acc[mi][ni][0] + c0, 0.f) + lfG[o0];
                v0.y = fmaxf(acc[mi][ni][1] + c1, 0.f) + lfG[o0 + 1];
                v1.x = fmaxf(acc[mi][ni][2] + c0, 0.f) + lfG[o1];
                v1.y = fmaxf(acc[mi][ni][3] + c1, 0.f) + lfG[o1 + 1];
                *(float2*)(C + o0) = v0;
                *(float2*)(C + o1) = v1;
            }
        }
    }
}

// Big GEMM wrapper: operands pre-rounded to tf32 -> no consume cvt.
// Grid: x = N-tile (fast -> L2 A reuse), y = M-tile. Dynamic smem (56.8 KB).
template <bool CONCAT, bool FUSE>
__global__ __launch_bounds__(256, 2) void gemm_big(
    const float* __restrict__ A, int lda,
    const float* __restrict__ A2,
    const float* __restrict__ B, int ldb,
    float* __restrict__ C, int ldc, int K,
    const float* __restrict__ cvec,
    const float* __restrict__ lfG)
{
    extern __shared__ float smem[];
    float* sA = smem;
    float* sB = smem + SMEM_FLOATS_A;
    gemm_body<false, CONCAT, FUSE, false, false>(
        A, lda, A2, B, ldb, C, ldc, K, 1.f,
        cvec, lfG, blockIdx.x, blockIdx.y, sA, sB);
}

// Fused precompute (2104 blocks):
//   0-15    M3 = Wq@Wk^T          (tf32-rounded store)
//   16-31   Mcat_top = Wv@Wf_top  (tf32-rounded store)
//   32-47   Mcat_bot = S*Wv@Wf_b  (tf32-rounded store)
//   48-55   cvec reduction
//   56+     g_Gt = f2tf(G)        (2048 blocks)
__global__ __launch_bounds__(256, 2) void k_pre(
    const float* __restrict__ Wq, const float* __restrict__ Wk,
    const float* __restrict__ Wv, const float* __restrict__ bv,
    const float* __restrict__ Wf, const float* __restrict__ bf,
    const float* __restrict__ wdr, const float* __restrict__ bdr,
    const float* __restrict__ G)
{
    extern __shared__ float smem[];
    float* sA = smem;
    float* sB = smem + SMEM_FLOATS_A;
    const int b = blockIdx.x;
    if (b < 48) {
        const int g = b & 15;
        const int bx = g & 3, by = g >> 2;   // 4 N-tiles x 4 M-tiles (512x512)
        if (b < 16) {
            gemm_body<true, false, false, true, true>(
                Wq, NH, nullptr, Wk, NH, g_M3, NF, NH,
                1.f, nullptr, nullptr, bx, by, sA, sB);
        } else if (b < 32) {
            gemm_body<false, false, false, true, true>(
                Wv, NH, nullptr, Wf, NF, g_Mcat, NF, NH,
                1.f, nullptr, nullptr, bx, by, sA, sB);
        } else {
            float S = 0.f;
#pragma unroll
            for (int k = 0; k < NLOC; k++) S += wdr[k];
            gemm_body<false, false, false, true, true>(
                Wv, NH, nullptr, Wf + (size_t)NH * NF, NF,
                g_Mcat + (size_t)NF * NF, NF, NH,
                S, nullptr, nullptr, bx, by, sA, sB);
        }
    } else if (b < 56) {
        // cvec: c[f] = bf + bv@Wf_top + S*bv@Wf_bot + b_dr*colsum(Wf_bot)
        __shared__ float red[3][4][64];
        const int t = threadIdx.x;
        const int fl = t & 63;
        const int f = (b - 48) * 64 + fl;
        const int hc = t >> 6;
        float a1 = 0.f, a2 = 0.f, a3 = 0.f;
        for (int h = hc * 64; h < hc * 64 + 64; h++) {
            float w1 = Wf[(size_t)h * NF + f];
            float w2 = Wf[(size_t)(NH + h) * NF + f];
            float bvh = bv[h];
            a1 += bvh * w1;
            a2 += bvh * w2;
            a3 += w2;
        }
        red[0][hc][fl] = a1;
        red[1][hc][fl] = a2;
        red[2][hc][fl] = a3;
        __syncthreads();
        if (hc == 0) {
            float s1 = red[0][0][fl] + red[0][1][fl] + red[0][2][fl] + red[0][3][fl];
            float s2 = red[1][0][fl] + red[1][1][fl] + red[1][2][fl] + red[1][3][fl];
            float s3 = red[2][0][fl] + red[2][1][fl] + red[2][2][fl] + red[2][3][fl];
            float S = 0.f;
#pragma unroll
            for (int k = 0; k < NLOC; k++) S += wdr[k];
            g_c[f] = bf[f] + s1 + S * s2 + (*bdr) * s3;
        }
    } else {
        // g_Gt = f2tf(G): 2048 blocks x 256 threads x 4 strided float4 = 8M floats
        const float4* src = (const float4*)G;
        float4* dst = (float4*)g_Gt;
#pragma unroll
        for (int i = 0; i < 4; i++) {
            size_t idx = (size_t)(b - 56) * 256 + threadIdx.x + (size_t)i * 2048 * 256;
            float4 v = src[idx];
            float4 o;
            o.x = __uint_as_float(f2tf(v.x));
            o.y = __uint_as_float(f2tf(v.y));
            o.z = __uint_as_float(f2tf(v.z));
            o.w = __uint_as_float(f2tf(v.w));
            dst[idx] = o;
        }
    }
}

// Per-row: scores vs T, softmax over 12, pooled = sum a_k * local_k (tf32-rounded),
// lfG = sum w_dr_k * local_k + b_dr + G   (local read exactly once via smem)
__global__ __launch_bounds__(128) void k_attn(
    const float* __restrict__ G, const float* __restrict__ L,
    const float* __restrict__ wdr, const float* __restrict__ bdr)
{
    __shared__ float4 sL[NLOC * 128];
    __shared__ float4 sT[128];
    __shared__ float sd[NLOC];
    const int b = blockIdx.x, tid = threadIdx.x;
    const float4* Lr = (const float4*)(L + (size_t)b * NLOC * NF);
    sT[tid] = ((const float4*)(g_T + (size_t)b * NF))[tid];
#pragma unroll
    for (int k = 0; k < NLOC; k++) sL[k * 128 + tid] = Lr[k * 128 + tid];
    __syncthreads();

    const int warp = tid >> 5, lane = tid & 31;
#pragma unroll
    for (int kk = 0; kk < 3; kk++) {
        int k = warp * 3 + kk;
        float s = 0.f;
#pragma unroll
        for (int j = 0; j < 4; j++) {
            float4 x = sL[k * 128 + lane + j * 32];
            float4 t = sT[lane + j * 32];
            s += x.x * t.x + x.y * t.y + x.z * t.z + x.w * t.w;
        }
#pragma unroll
        for (int o = 16; o; o >>= 1) s += __shfl_xor_sync(0xffffffffu, s, o);
        if (lane == 0) sd[k] = s;
    }
    __syncthreads();

    float a[NLOC], mx = -1e30f;
#pragma unroll
    for (int k = 0; k < NLOC; k++) mx = fmaxf(mx, sd[k]);
    float sum = 0.f;
#pragma unroll
    for (int k = 0; k < NLOC; k++) { a[k] = __expf((sd[k] - mx) * SCALE); sum += a[k]; }
    float inv = 1.f / sum;

    float4 p = make_float4(0, 0, 0, 0), q = make_float4(0, 0, 0, 0);
#pragma unroll
    for (int k = 0; k < NLOC; k++) {
        float ak = a[k] * inv, wk = wdr[k];
        float4 x = sL[k * 128 + tid];
        p.x += ak * x.x; p.y += ak * x.y; p.z += ak * x.z; p.w += ak * x.w;
        q.x += wk * x.x; q.y += wk * x.y; q.z += wk * x.z; q.w += wk * x.w;
    }
    float bd = *bdr;
    float4 g = ((const float4*)(G + (size_t)b * NF))[tid];
    float4 pt;
    pt.x = __uint_as_float(f2tf(p.x));
    pt.y = __uint_as_float(f2tf(p.y));
    pt.z = __uint_as_float(f2tf(p.z));
    pt.w = __uint_as_float(f2tf(p.w));
    ((float4*)(g_pooled + (size_t)b * NF))[tid] = pt;
    float4 o;
    o.x = q.x + bd + g.x; o.y = q.y + bd + g.y;
    o.z = q.z + bd + g.z; o.w = q.w + bd + g.w;
    ((float4*)(g_lfG + (size_t)b * NF))[tid] = o;
}

extern "C" void kernel_launch(void* const* d_in, const int* in_sizes, int n_in,
                              void* d_out, int out_size)
{
    const float* G   = (const float*)d_in[0];
    const float* L   = (const float*)d_in[1];
    const float* Wq  = (const float*)d_in[2];
    // d_in[3] = bq (unused: drops out of softmax)
    const float* Wk  = (const float*)d_in[4];
    // d_in[5] = bk (unused: k-independent score shift cancels in softmax)
    const float* Wv  = (const float*)d_in[6];
    const float* bv  = (const float*)d_in[7];
    const float* wdr = (const float*)d_in[8];
    const float* bdr = (const float*)d_in[9];
    const float* Wf  = (const float*)d_in[10];
    const float* bf  = (const float*)d_in[11];
    float* out = (float*)d_out;

    float *T, *P, *LF, *Gt, *M3, *Mcat, *cvec;
    cudaGetSymbolAddress((void**)&T, g_T);
    cudaGetSymbolAddress((void**)&P, g_pooled);
    cudaGetSymbolAddress((void**)&LF, g_lfG);
    cudaGetSymbolAddress((void**)&Gt, g_Gt);
    cudaGetSymbolAddress((void**)&M3, g_M3);
    cudaGetSymbolAddress((void**)&Mcat, g_Mcat);
    cudaGetSymbolAddress((void**)&cvec, g_c);

    // Opt-in to >48KB dynamic smem (attribute set, not an allocation)
    cudaFuncSetAttribute(gemm_big<false, false>,
                         cudaFuncAttributeMaxDynamicSharedMemorySize, SMEM_BYTES);
    cudaFuncSetAttribute(gemm_big<true, true>,
                         cudaFuncAttributeMaxDynamicSharedMemorySize, SMEM_BYTES);
    cudaFuncSetAttribute(k_pre,
                         cudaFuncAttributeMaxDynamicSharedMemorySize, SMEM_BYTES);

    dim3 blk(256);
    dim3 gbig(NF / BN, NB / BM);   // x = N-tiles (4), y = M-tiles (128)

    // 1) fused precompute: M3, Mcat, cvec, and g_Gt = f2tf(G)  [one launch]
    k_pre<<<56 + 2048, blk, SMEM_BYTES>>>(Wq, Wk, Wv, bv, Wf, bf, wdr, bdr, G);

    // 2) T = Gt @ M3   [16384,512] x [512,512]   (pre-rounded operands)
    gemm_big<false, false><<<gbig, blk, SMEM_BYTES>>>(
        Gt, NF, nullptr, M3, NF, T, NF, NF, nullptr, nullptr);

    // 3) per-row softmax / pooling (reads local_features once)
    k_attn<<<NB, 128>>>(G, L, wdr, bdr);

    // 4) OUT = relu([pooled | Gt] @ Mcat + c) + lfG   [16384,1024] x [1024,512]
    gemm_big<true, true><<<gbig, blk, SMEM_BYTES>>>(
        P, NF, Gt, Mcat, NF, out, NF, 2 * NF, cvec, LF);
}